// round 2
// baseline (speedup 1.0000x reference)
#include <cuda_runtime.h>
#include <cstdint>

// Problem shape (fixed by reference setup_inputs)
#define Bn 4
#define Cn 32
#define Hn 480
#define Wn 854
#define HWn (Hn * Wn)          // 409920
#define CHWn (Cn * HWn)
#define NPIX (Bn * HWn)        // 1639680
#define Kmax 10
#define OVF_CAP (1 << 20)

// ---------------------------------------------------------------------------
// Global scratch (static __device__ arrays: the allowed scratch mechanism).
// Per-destination contribution lists, built once per pixel (channel-agnostic),
// consumed 32x (once per channel). Layout [slot * NPIX + dst] so pass B reads
// are coalesced across a warp of consecutive dest pixels.
// ---------------------------------------------------------------------------
__device__ int      g_cnt[NPIX];           // contributions per dest pixel
__device__ float    g_w  [Kmax * NPIX];    // weight per entry
__device__ unsigned g_src[Kmax * NPIX];    // (srcY << 16) | srcX
__device__ int      g_ovf_n;
__device__ int      g_ovf_dst[OVF_CAP];
__device__ int      g_ovf_src[OVF_CAP];
__device__ float    g_ovf_w  [OVF_CAP];

// ---------------------------------------------------------------------------
// Reset counters (graph replays require re-init every launch).
// ---------------------------------------------------------------------------
__global__ void reset_kernel() {
    int i = blockIdx.x * blockDim.x + threadIdx.x;
    int stride = gridDim.x * blockDim.x;
    for (; i < NPIX; i += stride) g_cnt[i] = 0;
    if (blockIdx.x == 0 && threadIdx.x == 0) g_ovf_n = 0;
}

// ---------------------------------------------------------------------------
// Pass A: per source pixel, compute 4 bilinear corners and push
// (weight, src coords) into the destination cell's list. Channel-agnostic:
// 6.6M small atomics total instead of 157M RED lanes.
// ---------------------------------------------------------------------------
__global__ void __launch_bounds__(256) build_kernel(const float2* __restrict__ flow) {
    int pix = blockIdx.x * blockDim.x + threadIdx.x;
    if (pix >= NPIX) return;

    int b = pix / HWn;
    int p = pix - b * HWn;
    int y = p / Wn;
    int x = p - y * Wn;

    float2 f = flow[pix];
    float tx = (float)x + f.x;
    float ty = (float)y + f.y;
    float x0f = floorf(tx);
    float y0f = floorf(ty);
    float fx = tx - x0f;
    float fy = ty - y0f;
    int x0 = (int)x0f;
    int y0 = (int)y0f;

    float wx[2] = {1.f - fx, fx};
    float wy[2] = {1.f - fy, fy};
    unsigned sp = ((unsigned)y << 16) | (unsigned)x;

    #pragma unroll
    for (int cy = 0; cy < 2; cy++) {
        int yi = y0 + cy;
        if ((unsigned)yi >= (unsigned)Hn) continue;
        #pragma unroll
        for (int cx = 0; cx < 2; cx++) {
            int xi = x0 + cx;
            if ((unsigned)xi >= (unsigned)Wn) continue;
            float w = wx[cx] * wy[cy];
            int dst = b * HWn + yi * Wn + xi;
            int slot = atomicAdd(&g_cnt[dst], 1);
            if (slot < Kmax) {
                g_w  [slot * NPIX + dst] = w;
                g_src[slot * NPIX + dst] = sp;
            } else {
                int o = atomicAdd(&g_ovf_n, 1);
                if (o < OVF_CAP) {
                    g_ovf_dst[o] = dst;
                    g_ovf_src[o] = p;
                    g_ovf_w[o]   = w;
                }
            }
        }
    }
}

// ---------------------------------------------------------------------------
// Pass B: tiled gather. CTA = (b, 32x32 dest tile). Source region = tile +
// halo 16 (64x64), staged per channel in double-buffered SMEM. Each thread
// owns one dest pixel; its entry list (<=Kmax) is cached in registers across
// the 32-channel loop. Output written with plain stores (no atomics, no
// zero-init needed: tiles exactly cover the output).
// ---------------------------------------------------------------------------
#define TILE 32
#define HALO 16
#define RS 64                      // region size = TILE + 2*HALO
#define NF2 ((RS * RS) / 2)        // 2048 float2 per region

__global__ void __launch_bounds__(1024) gather_kernel(
    const float* __restrict__ im0, float* __restrict__ out)
{
    __shared__ float2 stage[2][NF2];

    const int tid = threadIdx.x;
    const int b = blockIdx.z;
    const int tx0 = blockIdx.x * TILE;
    const int ty0 = blockIdx.y * TILE;
    const int rx0 = tx0 - HALO;
    const int ry0 = ty0 - HALO;

    const int dtx = tid & 31;
    const int dty = tid >> 5;
    const int dx = tx0 + dtx;
    const int dy = ty0 + dty;
    const bool vd = (dx < Wn) && (dy < Hn);

    const float* __restrict__ imb = im0 + (size_t)b * CHWn;

    // Cache entries in registers (constant-index unrolled loop -> no spills).
    int cnt = 0;
    float ew[Kmax];
    unsigned eoff[Kmax];
    if (vd) {
        int dst = b * HWn + dy * Wn + dx;
        cnt = g_cnt[dst];
        if (cnt > Kmax) cnt = Kmax;
        #pragma unroll
        for (int j = 0; j < Kmax; j++) {
            if (j < cnt) {
                ew[j] = g_w[j * NPIX + dst];
                unsigned s = g_src[j * NPIX + dst];
                int sy = (int)(s >> 16) - ry0;
                int sx = (int)(s & 0xffffu) - rx0;
                if ((unsigned)sy < (unsigned)RS && (unsigned)sx < (unsigned)RS) {
                    eoff[j] = (unsigned)(sy * RS + sx);      // SMEM gather
                } else {
                    // rare far-flow entry: fall back to global load
                    eoff[j] = 0x80000000u | ((s >> 16) * Wn + (s & 0xffffu));
                }
            }
        }
    }

    // Staging addresses: thread loads float2 idx {tid, tid+1024} of the region.
    // float2 idx -> region row r = idx>>5, column pair c2 = idx&31.
    const int r0  = tid >> 5,          c20 = tid & 31;
    const int r1  = (tid + 1024) >> 5, c21 = tid & 31;   // (tid+1024)&31 == tid&31
    const int gy0 = ry0 + r0, gx0 = rx0 + c20 * 2;
    const int gy1 = ry0 + r1, gx1 = rx0 + c21 * 2;
    const bool v0 = ((unsigned)gy0 < (unsigned)Hn) && ((unsigned)gx0 < (unsigned)Wn);
    const bool v1 = ((unsigned)gy1 < (unsigned)Hn) && ((unsigned)gx1 < (unsigned)Wn);
    const float2* __restrict__ gp0 = (const float2*)(imb + (v0 ? (gy0 * Wn + gx0) : 0));
    const float2* __restrict__ gp1 = (const float2*)(imb + (v1 ? (gy1 * Wn + gx1) : 0));

    // Prologue: stage channel 0 into buffer 0.
    {
        float2 a0 = v0 ? __ldg(gp0) : make_float2(0.f, 0.f);
        float2 a1 = v1 ? __ldg(gp1) : make_float2(0.f, 0.f);
        stage[0][tid] = a0;
        stage[0][tid + 1024] = a1;
    }
    __syncthreads();

    for (int c = 0; c < Cn; c++) {
        // Prefetch next channel into registers (latency overlapped w/ gather).
        float2 n0, n1;
        if (c + 1 < Cn) {
            const int co = (c + 1) * (HWn / 2);
            n0 = v0 ? __ldg(gp0 + co) : make_float2(0.f, 0.f);
            n1 = v1 ? __ldg(gp1 + co) : make_float2(0.f, 0.f);
        }

        if (vd) {
            const float* stc = (const float*)stage[c & 1];
            const float* __restrict__ imc = imb + (size_t)c * HWn;
            float acc = 0.f;
            #pragma unroll
            for (int j = 0; j < Kmax; j++) {
                if (j < cnt) {
                    unsigned o = eoff[j];
                    float v = (o & 0x80000000u)
                                  ? __ldg(imc + (o & 0x7fffffffu))
                                  : stc[o];
                    acc = fmaf(ew[j], v, acc);
                }
            }
            out[(size_t)b * CHWn + (size_t)c * HWn + dy * Wn + dx] = acc;
        }

        if (c + 1 < Cn) {
            stage[(c + 1) & 1][tid] = n0;
            stage[(c + 1) & 1][tid + 1024] = n1;
        }
        __syncthreads();
    }
}

// ---------------------------------------------------------------------------
// Pass C: overflow entries (dest cells with >Kmax contributions; ~1e-3 of
// pixels). Adds on top of pass B's stored values with global atomics.
// ---------------------------------------------------------------------------
__global__ void ovf_kernel(const float* __restrict__ im0, float* __restrict__ out) {
    int n = g_ovf_n;
    if (n > OVF_CAP) n = OVF_CAP;
    for (int i = blockIdx.x * blockDim.x + threadIdx.x; i < n;
         i += gridDim.x * blockDim.x) {
        int dst = g_ovf_dst[i];
        int ps  = g_ovf_src[i];
        float w = g_ovf_w[i];
        int b = dst / HWn;
        int pd = dst - b * HWn;
        const float* ib = im0 + (size_t)b * CHWn + ps;
        float* ob = out + (size_t)b * CHWn + pd;
        #pragma unroll 4
        for (int c = 0; c < Cn; c++) {
            atomicAdd(ob + (size_t)c * HWn, w * ib[(size_t)c * HWn]);
        }
    }
}

// ---------------------------------------------------------------------------
// Harness entry: reset -> build lists -> tiled gather (plain stores) ->
// overflow cleanup. All launches, graph-capturable, no allocations.
// ---------------------------------------------------------------------------
extern "C" void kernel_launch(void* const* d_in, const int* in_sizes, int n_in,
                              void* d_out, int out_size) {
    const float*  im0  = (const float*)d_in[0];
    const float2* flow = (const float2*)d_in[1];
    float* out = (float*)d_out;

    reset_kernel<<<256, 256>>>();
    build_kernel<<<(NPIX + 255) / 256, 256>>>(flow);

    dim3 grid((Wn + TILE - 1) / TILE, (Hn + TILE - 1) / TILE, Bn);
    gather_kernel<<<grid, 1024>>>(im0, out);

    ovf_kernel<<<64, 256>>>(im0, out);
}